// round 13
// baseline (speedup 1.0000x reference)
#include <cuda_runtime.h>
#include <cuda_bf16.h>
#include <cuda_fp16.h>
#include <cstdint>

// B=16, Te=1024, Td=1024, D=1024
//   S'[b,t,e]  = dec[b,t,:] . enc[b,e,:]     (GEMM1, bf16 hi/lo 3-MMA split)
//   A'[t,e]    = row-softmax_e(S')           (contiguous softmax, fp16 pack)
//   ctx[b,t,d] = sum_e A'[t,e] enc[e,d]      (GEMM2, single fp16 MMA)
//   out        = concat(dec, ctx)            [B, Td, 2048]

#define PANEL_U4 1024  // one 128x64 x 2B SW128 panel = 16KB = 1024 uint4
#define NPANEL 2048    // 16 b * 8 rowblk * 16 kblk

__device__ float g_S[(size_t)16 * 1024 * 1024];  // fp32 scores S'[t,e]
__device__ uint4 g_encPh[NPANEL * PANEL_U4], g_encPl[NPANEL * PANEL_U4];  // enc bf16 h/l
__device__ uint4 g_decPh[NPANEL * PANEL_U4], g_decPl[NPANEL * PANEL_U4];  // dec bf16 h/l
__device__ uint4 g_encH[NPANEL * PANEL_U4];  // enc fp16 [e,d]
__device__ uint4 g_attH[NPANEL * PANEL_U4];  // attn fp16 [t,e]

// ---------------------------------------------------------------------------
static __device__ __forceinline__ uint32_t smem_u32(const void* p) {
  uint32_t a;
  asm("{ .reg .u64 t; cvta.to.shared.u64 t, %1; cvt.u32.u64 %0, t; }"
      : "=r"(a) : "l"(p));
  return a;
}
static __device__ __forceinline__ uint32_t swz(uint32_t x) {
  return x ^ ((x >> 3) & 0x70);
}
static __device__ __forceinline__ void cp_async16(uint32_t dst,
                                                  const void* src) {
  asm volatile("cp.async.cg.shared.global [%0], [%1], 16;"
               :: "r"(dst), "l"(src) : "memory");
}
static __device__ __forceinline__ void ldsm4(uint32_t* r, uint32_t addr) {
  asm volatile(
      "ldmatrix.sync.aligned.m8n8.x4.shared.b16 {%0,%1,%2,%3}, [%4];"
      : "=r"(r[0]), "=r"(r[1]), "=r"(r[2]), "=r"(r[3])
      : "r"(addr));
}
static __device__ __forceinline__ void ldsm4t(uint32_t* r, uint32_t addr) {
  asm volatile(
      "ldmatrix.sync.aligned.m8n8.x4.trans.shared.b16 {%0,%1,%2,%3}, [%4];"
      : "=r"(r[0]), "=r"(r[1]), "=r"(r[2]), "=r"(r[3])
      : "r"(addr));
}
static __device__ __forceinline__ void mma16816(float* c, const uint32_t* a,
                                                const uint32_t* b) {
  asm volatile(
      "mma.sync.aligned.m16n8k16.row.col.f32.bf16.bf16.f32 "
      "{%0,%1,%2,%3}, {%4,%5,%6,%7}, {%8,%9}, {%0,%1,%2,%3};"
      : "+f"(c[0]), "+f"(c[1]), "+f"(c[2]), "+f"(c[3])
      : "r"(a[0]), "r"(a[1]), "r"(a[2]), "r"(a[3]), "r"(b[0]), "r"(b[1]));
}
static __device__ __forceinline__ void mma16816h(float* c, const uint32_t* a,
                                                 const uint32_t* b) {
  asm volatile(
      "mma.sync.aligned.m16n8k16.row.col.f32.f16.f16.f32 "
      "{%0,%1,%2,%3}, {%4,%5,%6,%7}, {%8,%9}, {%0,%1,%2,%3};"
      : "+f"(c[0]), "+f"(c[1]), "+f"(c[2]), "+f"(c[3])
      : "r"(a[0]), "r"(a[1]), "r"(a[2]), "r"(a[3]), "r"(b[0]), "r"(b[1]));
}
static __device__ __forceinline__ uint32_t cvt_bf16x2(float hi, float lo) {
  uint32_t r;
  asm("cvt.rn.bf16x2.f32 %0, %1, %2;" : "=r"(r) : "f"(hi), "f"(lo));
  return r;
}
// bf16 hi/lo split, 2 elems/cvt
static __device__ __forceinline__ void split8(const float* f, uint4& H,
                                              uint4& L) {
  uint32_t h[4], l[4];
#pragma unroll
  for (int j = 0; j < 4; ++j) {
    const float f0 = f[2 * j], f1 = f[2 * j + 1];
    const uint32_t hu = cvt_bf16x2(f1, f0);  // lo half = f0
    const float fh0 = __uint_as_float(hu << 16);
    const float fh1 = __uint_as_float(hu & 0xFFFF0000u);
    h[j] = hu;
    l[j] = cvt_bf16x2(f1 - fh1, f0 - fh0);
  }
  H = make_uint4(h[0], h[1], h[2], h[3]);
  L = make_uint4(l[0], l[1], l[2], l[3]);
}
// fp16 pack of 8 floats
static __device__ __forceinline__ uint4 pack8h(const float* f) {
  uint32_t u[4];
#pragma unroll
  for (int j = 0; j < 4; ++j) {
    const __half2 h = __floats2half2_rn(f[2 * j], f[2 * j + 1]);
    u[j] = *reinterpret_cast<const uint32_t*>(&h);
  }
  return make_uint4(u[0], u[1], u[2], u[3]);
}

// ---------------------------------------------------------------------------
// Pack: fp32 [rows,1024] -> SW128 panels.
// grid (kb16, rb8, z32): z<16 -> enc (bf16 h/l + fp16); z>=16 -> dec (bf16 h/l)
// plus fused copy of dec into out[..., 0:1024].
// ---------------------------------------------------------------------------
__global__ __launch_bounds__(256) void conv_split_kernel(
    const float* __restrict__ enc, const float* __restrict__ dec,
    float* __restrict__ out) {
  const int kb = blockIdx.x, rb = blockIdx.y;
  const int which = blockIdx.z >> 4;
  const int b = blockIdx.z & 15;
  const float* src = which ? dec : enc;
  uint4* dh = which ? g_decPh : g_encPh;
  uint4* dl = which ? g_decPl : g_encPl;
  const size_t panel = ((size_t)(b * 8 + rb) * 16 + kb) * PANEL_U4;
  const float* sp = src + ((size_t)b * 1024 + rb * 128) * 1024 + kb * 64;
#pragma unroll
  for (int it = 0; it < 4; ++it) {
    const int chunk = it * 256 + threadIdx.x;
    const int r = chunk >> 3, cc = chunk & 7;
    const float4* s4 =
        reinterpret_cast<const float4*>(sp + (size_t)r * 1024 + cc * 8);
    float4 x0 = s4[0], x1 = s4[1];
    float f[8] = {x0.x, x0.y, x0.z, x0.w, x1.x, x1.y, x1.z, x1.w};
    uint4 H, L;
    split8(f, H, L);
    const uint32_t off = swz((uint32_t)(r * 128 + cc * 16)) >> 4;
    dh[panel + off] = H;
    dl[panel + off] = L;
    if (which) {
      float4* o4 = reinterpret_cast<float4*>(
          out + ((size_t)(b * 1024 + rb * 128 + r)) * 2048 + kb * 64 + cc * 8);
      o4[0] = x0;
      o4[1] = x1;
    } else {
      g_encH[panel + off] = pack8h(f);
    }
  }
}

// ---------------------------------------------------------------------------
// Row softmax of S'[t,e] + fp16 pack to attn panels [t-rowblk][e-kblk].
// One warp per t-row. grid (128, b=16), block 256 (8 warps = 8 rows).
// ---------------------------------------------------------------------------
__global__ __launch_bounds__(256) void softmax_pack_kernel() {
  const int b = blockIdx.y;
  const int t = blockIdx.x * 8 + (threadIdx.x >> 5);
  const int lane = threadIdx.x & 31;
  const float* Sr = g_S + ((size_t)b * 1024 + t) * 1024;

  float f[4][8];
  float m = -3.402823466e38f;
#pragma unroll
  for (int i = 0; i < 4; ++i) {
    const float4* p = reinterpret_cast<const float4*>(Sr + i * 256 + lane * 8);
    const float4 x0 = p[0], x1 = p[1];
    f[i][0] = x0.x; f[i][1] = x0.y; f[i][2] = x0.z; f[i][3] = x0.w;
    f[i][4] = x1.x; f[i][5] = x1.y; f[i][6] = x1.z; f[i][7] = x1.w;
#pragma unroll
    for (int j = 0; j < 8; ++j) m = fmaxf(m, f[i][j]);
  }
#pragma unroll
  for (int o = 16; o; o >>= 1)
    m = fmaxf(m, __shfl_xor_sync(0xffffffffu, m, o));

  float s = 0.f;
#pragma unroll
  for (int i = 0; i < 4; ++i)
#pragma unroll
    for (int j = 0; j < 8; ++j) {
      f[i][j] = __expf(f[i][j] - m);
      s += f[i][j];
    }
#pragma unroll
  for (int o = 16; o; o >>= 1) s += __shfl_xor_sync(0xffffffffu, s, o);
  const float inv = 1.f / s;

  const int tb = t >> 7, tl = t & 127;
  const uint32_t off = swz((uint32_t)(tl * 128 + (lane & 7) * 16)) >> 4;
#pragma unroll
  for (int i = 0; i < 4; ++i) {
#pragma unroll
    for (int j = 0; j < 8; ++j) f[i][j] *= inv;
    const int eb = i * 4 + (lane >> 3);
    const size_t panel = ((size_t)(b * 8 + tb) * 16 + eb) * PANEL_U4;
    g_attH[panel + off] = pack8h(f[i]);
  }
}

// ---------------------------------------------------------------------------
// GEMM1: S'[t,e] = dec . enc^T, bf16 hi/lo split (3 MMAs), C tile 128x64,
// K=1024, BK=64, 3-stage cp.async pipeline (wait_group 1: prefetch distance
// 2 chunks ~ fully hides gmem latency), 48KB/stage => 144KB, 1 CTA/SM.
// grid (nbk=16, mbk=8, b=16), 256 threads (8 warps: 4m x 2n, warp 32x32).
// ---------------------------------------------------------------------------
__global__ __launch_bounds__(256) void hmma_gemm1_kernel() {
  extern __shared__ __align__(16) char dsm[];
  const int tid = threadIdx.x;
  const int wid = tid >> 5, lane = tid & 31;
  const int wm = wid & 3, wn = wid >> 2;
  const int b = blockIdx.z, mbk = blockIdx.y, nbk = blockIdx.x;
  const size_t apan = ((size_t)(b * 8 + mbk)) * 16;
  const uint32_t smem_base = smem_u32(dsm);

  // stage (c%3)*48K: Ah 0..16K, Al 16K..32K, Bh 32K..40K, Bl 40K..48K
  auto issue_part = [&](int c, int j) {
    const uint32_t base = smem_base + (uint32_t)(c % 3) * 49152u;
    const uint4* a0 = g_decPh + (apan + c) * PANEL_U4;
    const uint4* a1 = g_decPl + (apan + c) * PANEL_U4;
    const int i = tid + j * 256;
    cp_async16(base + (uint32_t)i * 16u, a0 + i);
    cp_async16(base + 16384u + (uint32_t)i * 16u, a1 + i);
    if (j < 2) {
      const size_t bpan = ((size_t)(b * 8 + (nbk >> 1)) * 16 + c) * PANEL_U4;
      const int brow0 = (nbk & 1) * 64;
      const int lu = tid + j * 256;
      const int prow = brow0 + (lu >> 3), uin = lu & 7;
      cp_async16(base + 32768u + (uint32_t)lu * 16u,
                 g_encPh + bpan + prow * 8 + uin);
      cp_async16(base + 40960u + (uint32_t)lu * 16u,
                 g_encPl + bpan + prow * 8 + uin);
    }
  };

  float acc[2][4][4];
#pragma unroll
  for (int mt = 0; mt < 2; ++mt)
#pragma unroll
    for (int nt = 0; nt < 4; ++nt)
#pragma unroll
      for (int j = 0; j < 4; ++j) acc[mt][nt][j] = 0.f;

#pragma unroll
  for (int j = 0; j < 4; ++j) issue_part(0, j);
  asm volatile("cp.async.commit_group;" ::: "memory");
#pragma unroll
  for (int j = 0; j < 4; ++j) issue_part(1, j);
  asm volatile("cp.async.commit_group;" ::: "memory");

  const uint32_t a_row = (uint32_t)(wm * 32 + (lane & 15));
  const uint32_t a_koff = (lane & 16) ? 16u : 0u;
  const uint32_t b_row =
      (uint32_t)(wn * 32 + (lane & 7) + ((lane & 16) ? 8 : 0));
  const uint32_t b_koff = (lane & 8) ? 16u : 0u;

  for (int c = 0; c < 16; ++c) {
    asm volatile("cp.async.wait_group 1;" ::: "memory");
    __syncthreads();
    const uint32_t sb = smem_base + (uint32_t)(c % 3) * 49152u;
    const uint32_t Ah_b = sb, Al_b = sb + 16384u;
    const uint32_t Bh_b = sb + 32768u, Bl_b = sb + 40960u;

#pragma unroll
    for (int kk = 0; kk < 4; ++kk) {
      uint32_t ah[2][4], al[2][4];
#pragma unroll
      for (int mt = 0; mt < 2; ++mt) {
        const uint32_t byte = swz((a_row + (uint32_t)mt * 16u) * 128u +
                                  (uint32_t)kk * 32u + a_koff);
        ldsm4(ah[mt], Ah_b + byte);
        ldsm4(al[mt], Al_b + byte);
      }
      uint32_t bh[2][4], bl[2][4];
#pragma unroll
      for (int np = 0; np < 2; ++np) {
        const uint32_t byte = swz((b_row + (uint32_t)np * 16u) * 128u +
                                  (uint32_t)kk * 32u + b_koff);
        ldsm4(bh[np], Bh_b + byte);
        ldsm4(bl[np], Bl_b + byte);
      }
      // prefetch chunk c+2 into buffer (c+2)%3 == (c-1)%3: all warps
      // finished reading chunk c-1 (the barrier above is after compute(c-1))
      if (c + 2 < 16) issue_part(c + 2, kk);
#pragma unroll
      for (int mt = 0; mt < 2; ++mt)
#pragma unroll
        for (int nt = 0; nt < 4; ++nt) {
          const uint32_t* B0 = &bh[nt >> 1][(nt & 1) * 2];
          const uint32_t* B1 = &bl[nt >> 1][(nt & 1) * 2];
          mma16816(acc[mt][nt], ah[mt], B0);
          mma16816(acc[mt][nt], ah[mt], B1);
          mma16816(acc[mt][nt], al[mt], B0);
        }
    }
    asm volatile("cp.async.commit_group;" ::: "memory");
  }

  float* Cb = g_S + (size_t)b * 1024 * 1024 + (size_t)(mbk * 128) * 1024 +
              nbk * 64;
  const int g = lane >> 2, tig = lane & 3;
#pragma unroll
  for (int mt = 0; mt < 2; ++mt)
#pragma unroll
    for (int nt = 0; nt < 4; ++nt) {
      const int row = wm * 32 + mt * 16 + g;
      const int col = wn * 32 + nt * 8 + tig * 2;
      *reinterpret_cast<float2*>(Cb + (size_t)row * 1024 + col) =
          make_float2(acc[mt][nt][0], acc[mt][nt][1]);
      *reinterpret_cast<float2*>(Cb + (size_t)(row + 8) * 1024 + col) =
          make_float2(acc[mt][nt][2], acc[mt][nt][3]);
    }
}

// ---------------------------------------------------------------------------
// GEMM2: ctx[t,d] = attn . enc, SINGLE fp16 MMA (fp32 accumulate).
// C tile 128(M=t) x 128(N=d), warp tile 32x64 (8 warps: 4m x 2n).
// A = g_attH [t,e] panels (non-trans); B = g_encH [e,d] via ldmatrix.trans,
// two 64-col d-halves per chunk in separate 8KB blocks (one per n-warp).
// BK=64, 3-stage cp.async pipeline (wait_group 1), 32KB/stage => 96KB,
// 2 CTAs/SM. grid (nbk=8, mbk=8, b=16).
// ---------------------------------------------------------------------------
__global__ __launch_bounds__(256, 2) void hmma_gemm2_kernel(
    float* __restrict__ o) {
  extern __shared__ __align__(16) char dsm[];
  const int tid = threadIdx.x;
  const int wid = tid >> 5, lane = tid & 31;
  const int wm = wid & 3, wn = wid >> 2;
  const int b = blockIdx.z, mbk = blockIdx.y, nbk = blockIdx.x;
  const size_t apan = ((size_t)(b * 8 + mbk)) * 16;
  const uint32_t smem_base = smem_u32(dsm);

  // stage (c%3)*32K: A 0..16K, B 16K..32K ([dhalf 8KB][64 e-rows][128B])
  auto issue_part = [&](int c, int j) {
    const uint32_t base = smem_base + (uint32_t)(c % 3) * 32768u;
    const int i = tid + j * 256;
    cp_async16(base + (uint32_t)i * 16u, g_attH + (apan + c) * PANEL_U4 + i);
    const int lu = i;
    const int dhalf = lu >> 9, r = (lu >> 3) & 63, uin = lu & 7;
    const size_t bpan =
        ((size_t)(b * 8 + (c >> 1)) * 16 + nbk * 2 + dhalf) * PANEL_U4;
    const int prow = (c & 1) * 64 + r;
    cp_async16(base + 16384u + (uint32_t)lu * 16u,
               g_encH + bpan + prow * 8 + uin);
  };

  float acc[2][8][4];
#pragma unroll
  for (int mt = 0; mt < 2; ++mt)
#pragma unroll
    for (int nt = 0; nt < 8; ++nt)
#pragma unroll
      for (int j = 0; j < 4; ++j) acc[mt][nt][j] = 0.f;

#pragma unroll
  for (int j = 0; j < 4; ++j) issue_part(0, j);
  asm volatile("cp.async.commit_group;" ::: "memory");
#pragma unroll
  for (int j = 0; j < 4; ++j) issue_part(1, j);
  asm volatile("cp.async.commit_group;" ::: "memory");

  const uint32_t a_row = (uint32_t)(wm * 32 + (lane & 15));
  const uint32_t a_koff = (lane & 16) ? 16u : 0u;
  const uint32_t bt_krow = (uint32_t)(lane & 15);
  const uint32_t bt_coff = (lane & 16) ? 16u : 0u;  // within 64-col dhalf

  for (int c = 0; c < 16; ++c) {
    asm volatile("cp.async.wait_group 1;" ::: "memory");
    __syncthreads();
    const uint32_t sb = smem_base + (uint32_t)(c % 3) * 32768u;
    const uint32_t A_b = sb;
    const uint32_t B_b = sb + 16384u + (uint32_t)wn * 8192u;

#pragma unroll
    for (int kk = 0; kk < 4; ++kk) {
      uint32_t a[2][4];
#pragma unroll
      for (int mt = 0; mt < 2; ++mt) {
        const uint32_t byte = swz((a_row + (uint32_t)mt * 16u) * 128u +
                                  (uint32_t)kk * 32u + a_koff);
        ldsm4(a[mt], A_b + byte);
      }
      uint32_t bv[4][4];
#pragma unroll
      for (int np = 0; np < 4; ++np) {
        const uint32_t byte = swz(((uint32_t)kk * 16u + bt_krow) * 128u +
                                  bt_coff + (uint32_t)np * 32u);
        ldsm4t(bv[np], B_b + byte);
      }
      if (c + 2 < 16) issue_part(c + 2, kk);
#pragma unroll
      for (int mt = 0; mt < 2; ++mt)
#pragma unroll
        for (int nt = 0; nt < 8; ++nt)
          mma16816h(acc[mt][nt], a[mt], &bv[nt >> 1][(nt & 1) * 2]);
    }
    asm volatile("cp.async.commit_group;" ::: "memory");
  }

  float* Cb = o + (size_t)b * 1024 * 2048 + (size_t)(mbk * 128) * 2048 + 1024 +
              nbk * 128;
  const int g = lane >> 2, tig = lane & 3;
#pragma unroll
  for (int mt = 0; mt < 2; ++mt)
#pragma unroll
    for (int nt = 0; nt < 8; ++nt) {
      const int row = wm * 32 + mt * 16 + g;
      const int col = wn * 64 + nt * 8 + tig * 2;
      *reinterpret_cast<float2*>(Cb + (size_t)row * 2048 + col) =
          make_float2(acc[mt][nt][0], acc[mt][nt][1]);
      *reinterpret_cast<float2*>(Cb + (size_t)(row + 8) * 2048 + col) =
          make_float2(acc[mt][nt][2], acc[mt][nt][3]);
    }
}

// ---------------------------------------------------------------------------
extern "C" void kernel_launch(void* const* d_in, const int* in_sizes, int n_in,
                              void* d_out, int out_size) {
  const float* enc = (const float*)d_in[0];
  const float* dec = (const float*)d_in[1];
  float* out = (float*)d_out;

  cudaFuncSetAttribute(hmma_gemm1_kernel,
                       cudaFuncAttributeMaxDynamicSharedMemorySize, 147456);
  cudaFuncSetAttribute(hmma_gemm2_kernel,
                       cudaFuncAttributeMaxDynamicSharedMemorySize, 98304);

  dim3 cg(16, 8, 32);
  conv_split_kernel<<<cg, 256>>>(enc, dec, out);

  dim3 gg1(16, 8, 16);
  hmma_gemm1_kernel<<<gg1, 256, 147456>>>();

  softmax_pack_kernel<<<dim3(128, 16), 256>>>();

  dim3 gg2(8, 8, 16);
  hmma_gemm2_kernel<<<gg2, 256, 98304>>>(out);
}

// round 14
// speedup vs baseline: 1.1607x; 1.1607x over previous
#include <cuda_runtime.h>
#include <cuda_bf16.h>
#include <cuda_fp16.h>
#include <cstdint>

// B=16, Te=1024, Td=1024, D=1024
//   S'[b,t,e]  = dec[b,t,:] . enc[b,e,:]     (GEMM1, bf16 hi/lo 3-MMA split)
//   A'[t,e]    = row-softmax_e(S')           (contiguous softmax, fp16 pack)
//   ctx[b,t,d] = sum_e A'[t,e] enc[e,d]      (GEMM2, single fp16 MMA)
//   out        = concat(dec, ctx)            [B, Td, 2048]

#define PANEL_U4 1024  // one 128x64 x 2B SW128 panel = 16KB = 1024 uint4
#define NPANEL 2048    // 16 b * 8 rowblk * 16 kblk

__device__ float g_S[(size_t)16 * 1024 * 1024];  // fp32 scores S'[t,e]
__device__ uint4 g_encPh[NPANEL * PANEL_U4], g_encPl[NPANEL * PANEL_U4];  // enc bf16 h/l
__device__ uint4 g_decPh[NPANEL * PANEL_U4], g_decPl[NPANEL * PANEL_U4];  // dec bf16 h/l
__device__ uint4 g_encH[NPANEL * PANEL_U4];  // enc fp16 [e,d]
__device__ uint4 g_attH[NPANEL * PANEL_U4];  // attn fp16 [t,e]

// ---------------------------------------------------------------------------
static __device__ __forceinline__ uint32_t smem_u32(const void* p) {
  uint32_t a;
  asm("{ .reg .u64 t; cvta.to.shared.u64 t, %1; cvt.u32.u64 %0, t; }"
      : "=r"(a) : "l"(p));
  return a;
}
static __device__ __forceinline__ uint32_t swz(uint32_t x) {
  return x ^ ((x >> 3) & 0x70);
}
static __device__ __forceinline__ void cp_async16(uint32_t dst,
                                                  const void* src) {
  asm volatile("cp.async.cg.shared.global [%0], [%1], 16;"
               :: "r"(dst), "l"(src) : "memory");
}
static __device__ __forceinline__ void ldsm4(uint32_t* r, uint32_t addr) {
  asm volatile(
      "ldmatrix.sync.aligned.m8n8.x4.shared.b16 {%0,%1,%2,%3}, [%4];"
      : "=r"(r[0]), "=r"(r[1]), "=r"(r[2]), "=r"(r[3])
      : "r"(addr));
}
static __device__ __forceinline__ void ldsm4t(uint32_t* r, uint32_t addr) {
  asm volatile(
      "ldmatrix.sync.aligned.m8n8.x4.trans.shared.b16 {%0,%1,%2,%3}, [%4];"
      : "=r"(r[0]), "=r"(r[1]), "=r"(r[2]), "=r"(r[3])
      : "r"(addr));
}
static __device__ __forceinline__ void mma16816(float* c, const uint32_t* a,
                                                const uint32_t* b) {
  asm volatile(
      "mma.sync.aligned.m16n8k16.row.col.f32.bf16.bf16.f32 "
      "{%0,%1,%2,%3}, {%4,%5,%6,%7}, {%8,%9}, {%0,%1,%2,%3};"
      : "+f"(c[0]), "+f"(c[1]), "+f"(c[2]), "+f"(c[3])
      : "r"(a[0]), "r"(a[1]), "r"(a[2]), "r"(a[3]), "r"(b[0]), "r"(b[1]));
}
static __device__ __forceinline__ void mma16816h(float* c, const uint32_t* a,
                                                 const uint32_t* b) {
  asm volatile(
      "mma.sync.aligned.m16n8k16.row.col.f32.f16.f16.f32 "
      "{%0,%1,%2,%3}, {%4,%5,%6,%7}, {%8,%9}, {%0,%1,%2,%3};"
      : "+f"(c[0]), "+f"(c[1]), "+f"(c[2]), "+f"(c[3])
      : "r"(a[0]), "r"(a[1]), "r"(a[2]), "r"(a[3]), "r"(b[0]), "r"(b[1]));
}
static __device__ __forceinline__ uint32_t cvt_bf16x2(float hi, float lo) {
  uint32_t r;
  asm("cvt.rn.bf16x2.f32 %0, %1, %2;" : "=r"(r) : "f"(hi), "f"(lo));
  return r;
}
// bf16 hi/lo split, 2 elems/cvt
static __device__ __forceinline__ void split8(const float* f, uint4& H,
                                              uint4& L) {
  uint32_t h[4], l[4];
#pragma unroll
  for (int j = 0; j < 4; ++j) {
    const float f0 = f[2 * j], f1 = f[2 * j + 1];
    const uint32_t hu = cvt_bf16x2(f1, f0);  // lo half = f0
    const float fh0 = __uint_as_float(hu << 16);
    const float fh1 = __uint_as_float(hu & 0xFFFF0000u);
    h[j] = hu;
    l[j] = cvt_bf16x2(f1 - fh1, f0 - fh0);
  }
  H = make_uint4(h[0], h[1], h[2], h[3]);
  L = make_uint4(l[0], l[1], l[2], l[3]);
}
// fp16 pack of 8 floats
static __device__ __forceinline__ uint4 pack8h(const float* f) {
  uint32_t u[4];
#pragma unroll
  for (int j = 0; j < 4; ++j) {
    const __half2 h = __floats2half2_rn(f[2 * j], f[2 * j + 1]);
    u[j] = *reinterpret_cast<const uint32_t*>(&h);
  }
  return make_uint4(u[0], u[1], u[2], u[3]);
}

// ---------------------------------------------------------------------------
// Pack: fp32 [rows,1024] -> SW128 panels.
// grid (kb16, rb8, z32): z<16 -> enc (bf16 h/l + fp16); z>=16 -> dec (bf16 h/l)
// plus fused copy of dec into out[..., 0:1024].
// ---------------------------------------------------------------------------
__global__ __launch_bounds__(256) void conv_split_kernel(
    const float* __restrict__ enc, const float* __restrict__ dec,
    float* __restrict__ out) {
  const int kb = blockIdx.x, rb = blockIdx.y;
  const int which = blockIdx.z >> 4;
  const int b = blockIdx.z & 15;
  const float* src = which ? dec : enc;
  uint4* dh = which ? g_decPh : g_encPh;
  uint4* dl = which ? g_decPl : g_encPl;
  const size_t panel = ((size_t)(b * 8 + rb) * 16 + kb) * PANEL_U4;
  const float* sp = src + ((size_t)b * 1024 + rb * 128) * 1024 + kb * 64;
#pragma unroll
  for (int it = 0; it < 4; ++it) {
    const int chunk = it * 256 + threadIdx.x;
    const int r = chunk >> 3, cc = chunk & 7;
    const float4* s4 =
        reinterpret_cast<const float4*>(sp + (size_t)r * 1024 + cc * 8);
    float4 x0 = s4[0], x1 = s4[1];
    float f[8] = {x0.x, x0.y, x0.z, x0.w, x1.x, x1.y, x1.z, x1.w};
    uint4 H, L;
    split8(f, H, L);
    const uint32_t off = swz((uint32_t)(r * 128 + cc * 16)) >> 4;
    dh[panel + off] = H;
    dl[panel + off] = L;
    if (which) {
      float4* o4 = reinterpret_cast<float4*>(
          out + ((size_t)(b * 1024 + rb * 128 + r)) * 2048 + kb * 64 + cc * 8);
      o4[0] = x0;
      o4[1] = x1;
    } else {
      g_encH[panel + off] = pack8h(f);
    }
  }
}

// ---------------------------------------------------------------------------
// Row softmax of S'[t,e] + fp16 pack to attn panels [t-rowblk][e-kblk].
// One warp per t-row. grid (128, b=16), block 256 (8 warps = 8 rows).
// ---------------------------------------------------------------------------
__global__ __launch_bounds__(256) void softmax_pack_kernel() {
  const int b = blockIdx.y;
  const int t = blockIdx.x * 8 + (threadIdx.x >> 5);
  const int lane = threadIdx.x & 31;
  const float* Sr = g_S + ((size_t)b * 1024 + t) * 1024;

  float f[4][8];
  float m = -3.402823466e38f;
#pragma unroll
  for (int i = 0; i < 4; ++i) {
    const float4* p = reinterpret_cast<const float4*>(Sr + i * 256 + lane * 8);
    const float4 x0 = p[0], x1 = p[1];
    f[i][0] = x0.x; f[i][1] = x0.y; f[i][2] = x0.z; f[i][3] = x0.w;
    f[i][4] = x1.x; f[i][5] = x1.y; f[i][6] = x1.z; f[i][7] = x1.w;
#pragma unroll
    for (int j = 0; j < 8; ++j) m = fmaxf(m, f[i][j]);
  }
#pragma unroll
  for (int o = 16; o; o >>= 1)
    m = fmaxf(m, __shfl_xor_sync(0xffffffffu, m, o));

  float s = 0.f;
#pragma unroll
  for (int i = 0; i < 4; ++i)
#pragma unroll
    for (int j = 0; j < 8; ++j) {
      f[i][j] = __expf(f[i][j] - m);
      s += f[i][j];
    }
#pragma unroll
  for (int o = 16; o; o >>= 1) s += __shfl_xor_sync(0xffffffffu, s, o);
  const float inv = 1.f / s;

  const int tb = t >> 7, tl = t & 127;
  const uint32_t off = swz((uint32_t)(tl * 128 + (lane & 7) * 16)) >> 4;
#pragma unroll
  for (int i = 0; i < 4; ++i) {
#pragma unroll
    for (int j = 0; j < 8; ++j) f[i][j] *= inv;
    const int eb = i * 4 + (lane >> 3);
    const size_t panel = ((size_t)(b * 8 + tb) * 16 + eb) * PANEL_U4;
    g_attH[panel + off] = pack8h(f[i]);
  }
}

// ---------------------------------------------------------------------------
// GEMM1: S'[t,e] = dec . enc^T, bf16 hi/lo split (3 MMAs), C tile 128x64,
// K=1024, BK=64, 2-stage cp.async (interleaved issue), 48KB/stage => 96KB,
// 2 CTAs/SM. grid (nbk=16, mbk=8, b=16), 256 threads (8 warps: 4m x 2n).
// ---------------------------------------------------------------------------
__global__ __launch_bounds__(256, 2) void hmma_gemm1_kernel() {
  extern __shared__ __align__(16) char dsm[];
  const int tid = threadIdx.x;
  const int wid = tid >> 5, lane = tid & 31;
  const int wm = wid & 3, wn = wid >> 2;
  const int b = blockIdx.z, mbk = blockIdx.y, nbk = blockIdx.x;
  const size_t apan = ((size_t)(b * 8 + mbk)) * 16;
  const uint32_t smem_base = smem_u32(dsm);

  auto issue_part = [&](int c, int j) {
    const uint32_t base = smem_base + (uint32_t)(c & 1) * 49152u;
    const uint4* a0 = g_decPh + (apan + c) * PANEL_U4;
    const uint4* a1 = g_decPl + (apan + c) * PANEL_U4;
    const int i = tid + j * 256;
    cp_async16(base + (uint32_t)i * 16u, a0 + i);
    cp_async16(base + 16384u + (uint32_t)i * 16u, a1 + i);
    if (j < 2) {
      const size_t bpan = ((size_t)(b * 8 + (nbk >> 1)) * 16 + c) * PANEL_U4;
      const int brow0 = (nbk & 1) * 64;
      const int lu = tid + j * 256;
      const int prow = brow0 + (lu >> 3), uin = lu & 7;
      cp_async16(base + 32768u + (uint32_t)lu * 16u,
                 g_encPh + bpan + prow * 8 + uin);
      cp_async16(base + 40960u + (uint32_t)lu * 16u,
                 g_encPl + bpan + prow * 8 + uin);
    }
  };

  float acc[2][4][4];
#pragma unroll
  for (int mt = 0; mt < 2; ++mt)
#pragma unroll
    for (int nt = 0; nt < 4; ++nt)
#pragma unroll
      for (int j = 0; j < 4; ++j) acc[mt][nt][j] = 0.f;

#pragma unroll
  for (int j = 0; j < 4; ++j) issue_part(0, j);
  asm volatile("cp.async.commit_group;" ::: "memory");

  const uint32_t a_row = (uint32_t)(wm * 32 + (lane & 15));
  const uint32_t a_koff = (lane & 16) ? 16u : 0u;
  const uint32_t b_row =
      (uint32_t)(wn * 32 + (lane & 7) + ((lane & 16) ? 8 : 0));
  const uint32_t b_koff = (lane & 8) ? 16u : 0u;

  for (int c = 0; c < 16; ++c) {
    asm volatile("cp.async.wait_group 0;" ::: "memory");
    __syncthreads();
    const uint32_t sb = smem_base + (uint32_t)(c & 1) * 49152u;
    const uint32_t Ah_b = sb, Al_b = sb + 16384u;
    const uint32_t Bh_b = sb + 32768u, Bl_b = sb + 40960u;

#pragma unroll
    for (int kk = 0; kk < 4; ++kk) {
      uint32_t ah[2][4], al[2][4];
#pragma unroll
      for (int mt = 0; mt < 2; ++mt) {
        const uint32_t byte = swz((a_row + (uint32_t)mt * 16u) * 128u +
                                  (uint32_t)kk * 32u + a_koff);
        ldsm4(ah[mt], Ah_b + byte);
        ldsm4(al[mt], Al_b + byte);
      }
      uint32_t bh[2][4], bl[2][4];
#pragma unroll
      for (int np = 0; np < 2; ++np) {
        const uint32_t byte = swz((b_row + (uint32_t)np * 16u) * 128u +
                                  (uint32_t)kk * 32u + b_koff);
        ldsm4(bh[np], Bh_b + byte);
        ldsm4(bl[np], Bl_b + byte);
      }
      if (c + 1 < 16) issue_part(c + 1, kk);
#pragma unroll
      for (int mt = 0; mt < 2; ++mt)
#pragma unroll
        for (int nt = 0; nt < 4; ++nt) {
          const uint32_t* B0 = &bh[nt >> 1][(nt & 1) * 2];
          const uint32_t* B1 = &bl[nt >> 1][(nt & 1) * 2];
          mma16816(acc[mt][nt], ah[mt], B0);
          mma16816(acc[mt][nt], ah[mt], B1);
          mma16816(acc[mt][nt], al[mt], B0);
        }
    }
    asm volatile("cp.async.commit_group;" ::: "memory");
  }

  float* Cb = g_S + (size_t)b * 1024 * 1024 + (size_t)(mbk * 128) * 1024 +
              nbk * 64;
  const int g = lane >> 2, tig = lane & 3;
#pragma unroll
  for (int mt = 0; mt < 2; ++mt)
#pragma unroll
    for (int nt = 0; nt < 4; ++nt) {
      const int row = wm * 32 + mt * 16 + g;
      const int col = wn * 32 + nt * 8 + tig * 2;
      *reinterpret_cast<float2*>(Cb + (size_t)row * 1024 + col) =
          make_float2(acc[mt][nt][0], acc[mt][nt][1]);
      *reinterpret_cast<float2*>(Cb + (size_t)(row + 8) * 1024 + col) =
          make_float2(acc[mt][nt][2], acc[mt][nt][3]);
    }
}

// ---------------------------------------------------------------------------
// GEMM2: ctx[t,d] = attn . enc, SINGLE fp16 MMA (fp32 accumulate).
// C tile 128(M=t) x 128(N=d), warp tile 32x64 (8 warps: 4m x 2n).
// A = g_attH [t,e] panels (non-trans); B = g_encH [e,d] via ldmatrix.trans,
// two 64-col d-halves per chunk in separate 8KB blocks (one per n-warp).
// BK=64, 3-stage cp.async pipeline (wait_group 1), 32KB/stage => 96KB,
// 2 CTAs/SM. grid (nbk=8, mbk=8, b=16).
// ---------------------------------------------------------------------------
__global__ __launch_bounds__(256, 2) void hmma_gemm2_kernel(
    float* __restrict__ o) {
  extern __shared__ __align__(16) char dsm[];
  const int tid = threadIdx.x;
  const int wid = tid >> 5, lane = tid & 31;
  const int wm = wid & 3, wn = wid >> 2;
  const int b = blockIdx.z, mbk = blockIdx.y, nbk = blockIdx.x;
  const size_t apan = ((size_t)(b * 8 + mbk)) * 16;
  const uint32_t smem_base = smem_u32(dsm);

  // stage (c%3)*32K: A 0..16K, B 16K..32K ([dhalf 8KB][64 e-rows][128B])
  auto issue_part = [&](int c, int j) {
    const uint32_t base = smem_base + (uint32_t)(c % 3) * 32768u;
    const int i = tid + j * 256;
    cp_async16(base + (uint32_t)i * 16u, g_attH + (apan + c) * PANEL_U4 + i);
    const int lu = i;
    const int dhalf = lu >> 9, r = (lu >> 3) & 63, uin = lu & 7;
    const size_t bpan =
        ((size_t)(b * 8 + (c >> 1)) * 16 + nbk * 2 + dhalf) * PANEL_U4;
    const int prow = (c & 1) * 64 + r;
    cp_async16(base + 16384u + (uint32_t)lu * 16u,
               g_encH + bpan + prow * 8 + uin);
  };

  float acc[2][8][4];
#pragma unroll
  for (int mt = 0; mt < 2; ++mt)
#pragma unroll
    for (int nt = 0; nt < 8; ++nt)
#pragma unroll
      for (int j = 0; j < 4; ++j) acc[mt][nt][j] = 0.f;

#pragma unroll
  for (int j = 0; j < 4; ++j) issue_part(0, j);
  asm volatile("cp.async.commit_group;" ::: "memory");
#pragma unroll
  for (int j = 0; j < 4; ++j) issue_part(1, j);
  asm volatile("cp.async.commit_group;" ::: "memory");

  const uint32_t a_row = (uint32_t)(wm * 32 + (lane & 15));
  const uint32_t a_koff = (lane & 16) ? 16u : 0u;
  const uint32_t bt_krow = (uint32_t)(lane & 15);
  const uint32_t bt_coff = (lane & 16) ? 16u : 0u;  // within 64-col dhalf

  for (int c = 0; c < 16; ++c) {
    asm volatile("cp.async.wait_group 1;" ::: "memory");
    __syncthreads();
    const uint32_t sb = smem_base + (uint32_t)(c % 3) * 32768u;
    const uint32_t A_b = sb;
    const uint32_t B_b = sb + 16384u + (uint32_t)wn * 8192u;

#pragma unroll
    for (int kk = 0; kk < 4; ++kk) {
      uint32_t a[2][4];
#pragma unroll
      for (int mt = 0; mt < 2; ++mt) {
        const uint32_t byte = swz((a_row + (uint32_t)mt * 16u) * 128u +
                                  (uint32_t)kk * 32u + a_koff);
        ldsm4(a[mt], A_b + byte);
      }
      uint32_t bv[4][4];
#pragma unroll
      for (int np = 0; np < 4; ++np) {
        const uint32_t byte = swz(((uint32_t)kk * 16u + bt_krow) * 128u +
                                  bt_coff + (uint32_t)np * 32u);
        ldsm4t(bv[np], B_b + byte);
      }
      if (c + 2 < 16) issue_part(c + 2, kk);
#pragma unroll
      for (int mt = 0; mt < 2; ++mt)
#pragma unroll
        for (int nt = 0; nt < 8; ++nt)
          mma16816h(acc[mt][nt], a[mt], &bv[nt >> 1][(nt & 1) * 2]);
    }
    asm volatile("cp.async.commit_group;" ::: "memory");
  }

  float* Cb = o + (size_t)b * 1024 * 2048 + (size_t)(mbk * 128) * 2048 + 1024 +
              nbk * 128;
  const int g = lane >> 2, tig = lane & 3;
#pragma unroll
  for (int mt = 0; mt < 2; ++mt)
#pragma unroll
    for (int nt = 0; nt < 8; ++nt) {
      const int row = wm * 32 + mt * 16 + g;
      const int col = wn * 64 + nt * 8 + tig * 2;
      *reinterpret_cast<float2*>(Cb + (size_t)row * 2048 + col) =
          make_float2(acc[mt][nt][0], acc[mt][nt][1]);
      *reinterpret_cast<float2*>(Cb + (size_t)(row + 8) * 2048 + col) =
          make_float2(acc[mt][nt][2], acc[mt][nt][3]);
    }
}

// ---------------------------------------------------------------------------
extern "C" void kernel_launch(void* const* d_in, const int* in_sizes, int n_in,
                              void* d_out, int out_size) {
  const float* enc = (const float*)d_in[0];
  const float* dec = (const float*)d_in[1];
  float* out = (float*)d_out;

  cudaFuncSetAttribute(hmma_gemm1_kernel,
                       cudaFuncAttributeMaxDynamicSharedMemorySize, 98304);
  cudaFuncSetAttribute(hmma_gemm2_kernel,
                       cudaFuncAttributeMaxDynamicSharedMemorySize, 98304);

  dim3 cg(16, 8, 32);
  conv_split_kernel<<<cg, 256>>>(enc, dec, out);

  dim3 gg1(16, 8, 16);
  hmma_gemm1_kernel<<<gg1, 256, 98304>>>();

  softmax_pack_kernel<<<dim3(128, 16), 256>>>();

  dim3 gg2(8, 8, 16);
  hmma_gemm2_kernel<<<gg2, 256, 98304>>>(out);
}